// round 15
// baseline (speedup 1.0000x reference)
#include <cuda_runtime.h>
#include <cuda_fp16.h>
#include <cstdint>

// Problem constants
#define N_ATOMS 20000
#define N_EDGES 640000
#define NB      128
#define N_RBF   20

// -------- device scratch --------
__device__ __half g_hh[N_ATOMS * NB];      // h in fp16
__device__ float  g_agg[N_ATOMS * NB];
// packed weight fragments (filled by prep_kernel)
__device__ uint2 gPW1[2 * 16 * 32];        // edge layer1
__device__ uint4 gPW2[8 * 8 * 32];         // edge layer2 (nt-paired)
__device__ uint4 gPWH[8 * 8 * 32];         // h kernel W_in2f
__device__ uint4 gPO1[8 * 8 * 32];         // out layer1
__device__ uint4 gPO2[8 * 8 * 32];         // out layer2
// counting-sort scratch
__device__ int   g_cnt[N_ATOMS];           // counts -> exclusive offsets (cursor)
__device__ int   g_perm[N_EDGES];          // sorted position -> original edge id
__device__ int   g_iis[N_EDGES];           // idx_i in sorted order
__device__ int   g_jis[N_EDGES];           // idx_j in sorted order
__device__ float g_rcs[N_EDGES];           // rcut in sorted order

#define LN2F     0.69314718055994531f
#define LOG2EF   1.4426950408889634f
__device__ __forceinline__ float ssp_fast(float x) {
    float u = fabsf(x) * -LOG2EF;
    float e; asm("ex2.approx.f32 %0, %1;" : "=f"(e) : "f"(u));
    float l; asm("lg2.approx.f32 %0, %1;" : "=f"(l) : "f"(1.0f + e));
    return fmaf(LN2F, l - 1.0f, fmaxf(x, 0.0f));
}

__device__ __forceinline__ uint32_t h2pack(float lo, float hi) {
    __half2 h = __floats2half2_rn(lo, hi);
    return *(uint32_t*)&h;
}
__device__ __forceinline__ float2 h2unpack(uint32_t u) {
    __half2 h = *(__half2*)&u;
    return __half22float2(h);
}

// m16n8k16 f16 mma, f32 accumulate
__device__ __forceinline__ void mma_f16(float4& c,
                                        uint32_t a0, uint32_t a1, uint32_t a2, uint32_t a3,
                                        uint32_t b0, uint32_t b1) {
    asm volatile(
        "mma.sync.aligned.m16n8k16.row.col.f32.f16.f16.f32 "
        "{%0,%1,%2,%3}, {%4,%5,%6,%7}, {%8,%9}, {%0,%1,%2,%3};"
        : "+f"(c.x), "+f"(c.y), "+f"(c.z), "+f"(c.w)
        : "r"(a0), "r"(a1), "r"(a2), "r"(a3), "r"(b0), "r"(b1));
}

__device__ __forceinline__ void red_v4(float* p, float a, float b, float c, float d) {
    asm volatile("red.global.add.v4.f32 [%0], {%1, %2, %3, %4};"
                 :: "l"(p), "f"(a), "f"(b), "f"(c), "f"(d) : "memory");
}

// ======================= prep kernel: pack weights + zero counters =======================
__global__ void prep_kernel(const float* __restrict__ W1e, const float* __restrict__ W2e,
                            const float* __restrict__ Wh,  const float* __restrict__ Wo1,
                            const float* __restrict__ Wo2)
{
    const int tid = blockIdx.x * blockDim.x + threadIdx.x;
    const int stride = gridDim.x * blockDim.x;

    for (int i = tid; i < N_ATOMS; i += stride) g_cnt[i] = 0;

    for (int i = tid; i < 2 * 16 * 32; i += stride) {
        int p1 = i >> 9, nt = (i >> 5) & 15, l = i & 31;
        int gg = l >> 2, tt = l & 3;
        int n = nt * 8 + gg;
        int k0 = p1 * 16 + 2 * tt;
        float w00 = (k0     < N_RBF) ? W1e[k0 * NB + n]       : 0.0f;
        float w01 = (k0 + 1 < N_RBF) ? W1e[(k0 + 1) * NB + n] : 0.0f;
        float w10 = (k0 + 8 < N_RBF) ? W1e[(k0 + 8) * NB + n] : 0.0f;
        float w11 = (k0 + 9 < N_RBF) ? W1e[(k0 + 9) * NB + n] : 0.0f;
        uint2 v; v.x = h2pack(w00, w01); v.y = h2pack(w10, w11);
        gPW1[i] = v;
    }
    for (int i = tid; i < 8 * 8 * 32; i += stride) {
        int p = i >> 8, ntp = (i >> 5) & 7, l = i & 31;
        int gg = l >> 2, tt = l & 3;
        int k0 = p * 16 + 2 * tt;
        int nE = (2 * ntp) * 8 + gg, nO = nE + 8;
        uint4 v;
#define PACK4(W) do { \
        v.x = h2pack(W[k0 * NB + nE], W[(k0 + 1) * NB + nE]); \
        v.y = h2pack(W[(k0 + 8) * NB + nE], W[(k0 + 9) * NB + nE]); \
        v.z = h2pack(W[k0 * NB + nO], W[(k0 + 1) * NB + nO]); \
        v.w = h2pack(W[(k0 + 8) * NB + nO], W[(k0 + 9) * NB + nO]); } while (0)
        PACK4(W2e); gPW2[i] = v;
        PACK4(Wh);  gPWH[i] = v;
        PACK4(Wo1); gPO1[i] = v;
        PACK4(Wo2); gPO2[i] = v;
#undef PACK4
    }
}

// ======================= counting sort: hist -> scan -> scatter =======================
__global__ void hist_kernel(const int* __restrict__ idx_i) {
    for (int e = blockIdx.x * blockDim.x + threadIdx.x; e < N_EDGES;
         e += gridDim.x * blockDim.x)
        atomicAdd(&g_cnt[idx_i[e]], 1);
}

#define SCAN_T 1024
#define SCAN_CH ((N_ATOMS + SCAN_T - 1) / SCAN_T)   // 20
__global__ __launch_bounds__(SCAN_T) void scan_kernel() {
    __shared__ int part[SCAN_T];
    const int tid = threadIdx.x;
    const int base = tid * SCAN_CH;
    int local[SCAN_CH];
    int s = 0;
#pragma unroll
    for (int k = 0; k < SCAN_CH; k++) {
        int idx = base + k;
        int c = (idx < N_ATOMS) ? g_cnt[idx] : 0;
        local[k] = s; s += c;
    }
    part[tid] = s;
    __syncthreads();
    for (int off = 1; off < SCAN_T; off <<= 1) {
        int v = (tid >= off) ? part[tid - off] : 0;
        __syncthreads();
        part[tid] += v;
        __syncthreads();
    }
    const int excl = (tid == 0) ? 0 : part[tid - 1];
#pragma unroll
    for (int k = 0; k < SCAN_CH; k++) {
        int idx = base + k;
        if (idx < N_ATOMS) g_cnt[idx] = excl + local[k];
    }
}

__global__ void scatter_kernel(const int* __restrict__ idx_i,
                               const int* __restrict__ idx_j,
                               const float* __restrict__ rcut) {
    for (int e = blockIdx.x * blockDim.x + threadIdx.x; e < N_EDGES;
         e += gridDim.x * blockDim.x) {
        int ii = idx_i[e];
        int pos = atomicAdd(&g_cnt[ii], 1);
        g_perm[pos] = e;
        g_iis[pos]  = ii;
        g_jis[pos]  = idx_j[e];
        g_rcs[pos]  = rcut[e];
    }
}

// ======================= h kernel (fp16 mma) -> g_hh (half) + agg zeroing ================
#define HW 8
#define HT (HW * 32)
#define H_SMEMB (32768 + HW * 4224)

__global__ __launch_bounds__(HT, 1) void h_kernel(
    const float* __restrict__ x, float* __restrict__ agg)
{
    extern __shared__ char smc[];
    uint4* ws = (uint4*)smc;
    const int tid  = threadIdx.x;
    const int warp = tid >> 5;
    const int lane = tid & 31;
    const int g    = lane >> 2;
    const int t    = lane & 3;

    for (int i = tid; i < 2048; i += HT) ws[i] = gPWH[i];
    __syncthreads();

    __half* tw = (__half*)(smc + 32768 + warp * 4224);
    const int ngroups = N_ATOMS / 16;

    for (int grp = blockIdx.x * HW + warp; grp < ngroups; grp += gridDim.x * HW) {
        const int r0 = grp * 16;

        uint32_t af[8][4];
#pragma unroll
        for (int p = 0; p < 8; p++) {
            const float* r0p = x + (size_t)(r0 + g) * NB + p * 16;
            const float* r1p = r0p + 8 * NB;
            float2 x0 = *(const float2*)(r0p + 2 * t);
            float2 x1 = *(const float2*)(r1p + 2 * t);
            float2 x2 = *(const float2*)(r0p + 2 * t + 8);
            float2 x3 = *(const float2*)(r1p + 2 * t + 8);
            af[p][0] = h2pack(x0.x, x0.y);
            af[p][1] = h2pack(x1.x, x1.y);
            af[p][2] = h2pack(x2.x, x2.y);
            af[p][3] = h2pack(x3.x, x3.y);
        }

        float4 c[16];
#pragma unroll
        for (int nt = 0; nt < 16; nt++) c[nt] = make_float4(0.f, 0.f, 0.f, 0.f);
#pragma unroll
        for (int p = 0; p < 8; p++) {
            uint32_t a0 = af[p][0], a1 = af[p][1], a2 = af[p][2], a3 = af[p][3];
#pragma unroll
            for (int ntp = 0; ntp < 8; ntp++) {
                uint4 b = ws[(p * 8 + ntp) * 32 + lane];
                mma_f16(c[2 * ntp],     a0, a1, a2, a3, b.x, b.y);
                mma_f16(c[2 * ntp + 1], a0, a1, a2, a3, b.z, b.w);
            }
        }
        __syncwarp();

        {
            const int cq  = (t >> 1) * 4;
            const bool odd = (t & 1);
            const int srow = g + (odd ? 8 : 0);
#pragma unroll
            for (int nt = 0; nt < 16; nt++) {
                float s0 = odd ? c[nt].x : c[nt].z;
                float s1 = odd ? c[nt].y : c[nt].w;
                float r0s = __shfl_xor_sync(0xffffffffu, s0, 1);
                float r1s = __shfl_xor_sync(0xffffffffu, s1, 1);
                float4 v;
                if (!odd) { v.x = c[nt].x; v.y = c[nt].y; v.z = r0s; v.w = r1s; }
                else      { v.x = r0s; v.y = r1s; v.z = c[nt].z; v.w = c[nt].w; }
                uint2 pk; pk.x = h2pack(v.x, v.y); pk.y = h2pack(v.z, v.w);
                *(uint2*)(tw + srow * 132 + nt * 8 + cq) = pk;
            }
        }
        __syncwarp();

        const float4 z4 = make_float4(0.f, 0.f, 0.f, 0.f);
#pragma unroll 4
        for (int el = 0; el < 16; el++) {
            uint2 v = *(const uint2*)(tw + el * 132 + lane * 4);
            ((uint2*)(g_hh + (size_t)(r0 + el) * NB))[lane] = v;
            *(float4*)(agg + (size_t)(r0 + el) * NB + lane * 4) = z4;
        }
        __syncwarp();
    }
}

// ======================= fused edge kernel (sorted, segmented-reduce epilogue) ==========
#define EW 12
#define ET (EW * 32)
#define E_OUTB 41472
#define E_SMEMB (E_OUTB + EW * 8448)

__global__ __launch_bounds__(ET, 1) void edge_kernel(
    const float* __restrict__ f_ij,
    const float* __restrict__ b1, const float* __restrict__ b2)
{
    extern __shared__ char smc[];
    uint2* w1s = (uint2*)smc;
    uint4* w2s = (uint4*)(smc + 8192);
    float* b1s = (float*)(smc + 40960);
    const int tid  = threadIdx.x;
    const int warp = tid >> 5;
    const int lane = tid & 31;
    const int g    = lane >> 2;
    const int t    = lane & 3;

    for (int i = tid; i < 1024; i += ET) w1s[i] = gPW1[i];
    for (int i = tid; i < 2048; i += ET) w2s[i] = gPW2[i];
    for (int i = tid; i < NB; i += ET) b1s[i] = b1[i];
    __syncthreads();

    __half* outw = (__half*)(smc + E_OUTB + warp * 8448);  // 32 rows x 132 halfs
    const float4 b2v = *(const float4*)(b2 + lane * 4);
    const int cq  = (t >> 1) * 4;
    const bool odd = (t & 1);
    const int ngroups = N_EDGES / 32;  // 20000

    for (int grp = blockIdx.x * EW + warp; grp < ngroups; grp += gridDim.x * EW) {
        const int e0 = grp * 32;

        // sorted metadata (coalesced); perm for f gather
        const float rc_l = __ldg(g_rcs + e0 + lane);
        const int   ji_l = __ldg(g_jis + e0 + lane);
        const int   ii_l = __ldg(g_iis + e0 + lane);
        const int   pm_l = __ldg(g_perm + e0 + lane);

        // layer-1 A fragments gathered via perm
        uint32_t A[2][6];
#pragma unroll
        for (int s = 0; s < 2; s++) {
            const int pr0 = __shfl_sync(0xffffffffu, pm_l, 16 * s + g);
            const int pr8 = __shfl_sync(0xffffffffu, pm_l, 16 * s + g + 8);
            const float* fr0 = f_ij + (size_t)pr0 * N_RBF;
            const float* fr1 = f_ij + (size_t)pr8 * N_RBF;
            float2 q00 = *(const float2*)(fr0 + 2 * t);
            float2 q01 = *(const float2*)(fr1 + 2 * t);
            float2 q02 = *(const float2*)(fr0 + 2 * t + 8);
            float2 q03 = *(const float2*)(fr1 + 2 * t + 8);
            float2 q10 = make_float2(0.f, 0.f), q11 = make_float2(0.f, 0.f);
            if (t < 2) {
                q10 = *(const float2*)(fr0 + 2 * t + 16);
                q11 = *(const float2*)(fr1 + 2 * t + 16);
            }
            A[s][0] = h2pack(q00.x, q00.y); A[s][1] = h2pack(q01.x, q01.y);
            A[s][2] = h2pack(q02.x, q02.y); A[s][3] = h2pack(q03.x, q03.y);
            A[s][4] = h2pack(q10.x, q10.y); A[s][5] = h2pack(q11.x, q11.y);
        }

        // ---- layer 1 in quarters, both subsets share B loads ----
        uint32_t paf[2][8][4];
#pragma unroll
        for (int qt = 0; qt < 4; qt++) {
            float4 c1[2][4];
#pragma unroll
            for (int j = 0; j < 4; j++) {
                float2 bb = *(const float2*)(b1s + (4 * qt + j) * 8 + 2 * t);
#pragma unroll
                for (int s = 0; s < 2; s++) {
                    c1[s][j].x = bb.x; c1[s][j].y = bb.y;
                    c1[s][j].z = bb.x; c1[s][j].w = bb.y;
                }
            }
#pragma unroll
            for (int j = 0; j < 4; j++) {
                const int nt = 4 * qt + j;
                uint2 b0  = w1s[nt * 32 + lane];
                uint2 b1f = w1s[(16 + nt) * 32 + lane];
#pragma unroll
                for (int s = 0; s < 2; s++) {
                    mma_f16(c1[s][j], A[s][0], A[s][1], A[s][2], A[s][3], b0.x, b0.y);
                    mma_f16(c1[s][j], A[s][4], A[s][5], 0u, 0u, b1f.x, b1f.y);
                }
            }
#pragma unroll
            for (int s = 0; s < 2; s++)
#pragma unroll
                for (int jj = 0; jj < 2; jj++) {
                    const int p = 2 * qt + jj;
                    paf[s][p][0] = h2pack(ssp_fast(c1[s][2 * jj].x),     ssp_fast(c1[s][2 * jj].y));
                    paf[s][p][1] = h2pack(ssp_fast(c1[s][2 * jj].z),     ssp_fast(c1[s][2 * jj].w));
                    paf[s][p][2] = h2pack(ssp_fast(c1[s][2 * jj + 1].x), ssp_fast(c1[s][2 * jj + 1].y));
                    paf[s][p][3] = h2pack(ssp_fast(c1[s][2 * jj + 1].z), ssp_fast(c1[s][2 * jj + 1].w));
                }
        }
        __syncwarp();   // previous group's outw fully consumed

        // ---- layer 2 in quarters; pair-swap each quarter to fp16 outw ----
#pragma unroll
        for (int qt = 0; qt < 4; qt++) {
            float4 c2[2][4];
#pragma unroll
            for (int s = 0; s < 2; s++)
#pragma unroll
                for (int j = 0; j < 4; j++) c2[s][j] = make_float4(0.f, 0.f, 0.f, 0.f);
#pragma unroll
            for (int p = 0; p < 8; p++) {
#pragma unroll
                for (int jj = 0; jj < 2; jj++) {
                    const int ntp = 2 * qt + jj;
                    uint4 b = w2s[(p * 8 + ntp) * 32 + lane];
#pragma unroll
                    for (int s = 0; s < 2; s++) {
                        mma_f16(c2[s][2 * jj],     paf[s][p][0], paf[s][p][1],
                                paf[s][p][2], paf[s][p][3], b.x, b.y);
                        mma_f16(c2[s][2 * jj + 1], paf[s][p][0], paf[s][p][1],
                                paf[s][p][2], paf[s][p][3], b.z, b.w);
                    }
                }
            }
#pragma unroll
            for (int s = 0; s < 2; s++) {
                const int row = 16 * s + g + (odd ? 8 : 0);
#pragma unroll
                for (int j = 0; j < 4; j++) {
                    const int nt = 4 * qt + j;
                    float s0 = odd ? c2[s][j].x : c2[s][j].z;
                    float s1 = odd ? c2[s][j].y : c2[s][j].w;
                    float r0 = __shfl_xor_sync(0xffffffffu, s0, 1);
                    float r1 = __shfl_xor_sync(0xffffffffu, s1, 1);
                    float4 v;
                    if (!odd) { v.x = c2[s][j].x; v.y = c2[s][j].y; v.z = r0; v.w = r1; }
                    else      { v.x = r0; v.y = r1; v.z = c2[s][j].z; v.w = c2[s][j].w; }
                    uint2 pk; pk.x = h2pack(v.x, v.y); pk.y = h2pack(v.z, v.w);
                    *(uint2*)(outw + row * 132 + nt * 8 + cq) = pk;
                }
            }
        }
        __syncwarp();

        // ---- segmented epilogue: accumulate rows while ii constant, RED per segment ----
        {
            float4 acc = make_float4(0.f, 0.f, 0.f, 0.f);
            int cur = __shfl_sync(0xffffffffu, ii_l, 0);
#pragma unroll 4
            for (int el = 0; el < 32; el++) {
                int   ii = __shfl_sync(0xffffffffu, ii_l, el);
                float rc = __shfl_sync(0xffffffffu, rc_l, el);
                int   ji = __shfl_sync(0xffffffffu, ji_l, el);
                if (ii != cur) {
                    red_v4(g_agg + (size_t)cur * NB + lane * 4,
                           acc.x, acc.y, acc.z, acc.w);
                    acc = make_float4(0.f, 0.f, 0.f, 0.f);
                    cur = ii;
                }
                uint2 pv = *(const uint2*)(outw + el * 132 + lane * 4);
                float2 f0 = h2unpack(pv.x), f1 = h2unpack(pv.y);
                uint2 ph = __ldg((const uint2*)(g_hh + (size_t)ji * NB) + lane);
                float2 g0 = h2unpack(ph.x), g1 = h2unpack(ph.y);
                acc.x += (f0.x + b2v.x) * rc * g0.x;
                acc.y += (f0.y + b2v.y) * rc * g0.y;
                acc.z += (f1.x + b2v.z) * rc * g1.x;
                acc.w += (f1.y + b2v.w) * rc * g1.y;
            }
            red_v4(g_agg + (size_t)cur * NB + lane * 4, acc.x, acc.y, acc.z, acc.w);
        }
        __syncwarp();
    }
}

// ======================= fused out kernel (fp16 mma) =======================
#define OW 12
#define OT (OW * 32)
#define O_TWB 66560
#define O_SMEMB (O_TWB + OW * 8448)

__global__ __launch_bounds__(OT, 1) void out_kernel(
    const float* __restrict__ A,     // g_agg
    const float* __restrict__ b1, const float* __restrict__ b2,
    float* __restrict__ out)
{
    extern __shared__ char smc[];
    uint4* w1s = (uint4*)smc;
    uint4* w2s = (uint4*)(smc + 32768);
    float* b1s = (float*)(smc + 65536);
    float* b2s = (float*)(smc + 66048);
    const int tid  = threadIdx.x;
    const int warp = tid >> 5;
    const int lane = tid & 31;
    const int g    = lane >> 2;
    const int t    = lane & 3;

    for (int i = tid; i < 2048; i += OT) { w1s[i] = gPO1[i]; w2s[i] = gPO2[i]; }
    for (int i = tid; i < NB; i += OT) { b1s[i] = b1[i]; b2s[i] = b2[i]; }
    __syncthreads();

    float* tw = (float*)(smc + O_TWB + warp * 8448);
    const int ngroups = N_ATOMS / 16;   // 1250

    for (int grp = blockIdx.x * OW + warp; grp < ngroups; grp += gridDim.x * OW) {
        const int r0 = grp * 16;

        uint32_t af[8][4];
#pragma unroll
        for (int p = 0; p < 8; p++) {
            const float* r0p = A + (size_t)(r0 + g) * NB + p * 16;
            const float* r1p = r0p + 8 * NB;
            float2 x0 = *(const float2*)(r0p + 2 * t);
            float2 x1 = *(const float2*)(r1p + 2 * t);
            float2 x2 = *(const float2*)(r0p + 2 * t + 8);
            float2 x3 = *(const float2*)(r1p + 2 * t + 8);
            af[p][0] = h2pack(x0.x, x0.y);
            af[p][1] = h2pack(x1.x, x1.y);
            af[p][2] = h2pack(x2.x, x2.y);
            af[p][3] = h2pack(x3.x, x3.y);
        }

        float4 c1[16];
#pragma unroll
        for (int nt = 0; nt < 16; nt++) {
            float2 bb = *(const float2*)(b1s + nt * 8 + 2 * t);
            c1[nt].x = bb.x; c1[nt].y = bb.y;
            c1[nt].z = bb.x; c1[nt].w = bb.y;
        }
#pragma unroll
        for (int p = 0; p < 8; p++) {
            uint32_t a0 = af[p][0], a1 = af[p][1], a2 = af[p][2], a3 = af[p][3];
#pragma unroll
            for (int ntp = 0; ntp < 8; ntp++) {
                uint4 b = w1s[(p * 8 + ntp) * 32 + lane];
                mma_f16(c1[2 * ntp],     a0, a1, a2, a3, b.x, b.y);
                mma_f16(c1[2 * ntp + 1], a0, a1, a2, a3, b.z, b.w);
            }
        }

        uint32_t paf[8][4];
#pragma unroll
        for (int p = 0; p < 8; p++) {
            paf[p][0] = h2pack(ssp_fast(c1[2 * p].x),     ssp_fast(c1[2 * p].y));
            paf[p][1] = h2pack(ssp_fast(c1[2 * p].z),     ssp_fast(c1[2 * p].w));
            paf[p][2] = h2pack(ssp_fast(c1[2 * p + 1].x), ssp_fast(c1[2 * p + 1].y));
            paf[p][3] = h2pack(ssp_fast(c1[2 * p + 1].z), ssp_fast(c1[2 * p + 1].w));
        }

        float4 c2[16];
#pragma unroll
        for (int nt = 0; nt < 16; nt++) {
            float2 bb = *(const float2*)(b2s + nt * 8 + 2 * t);
            c2[nt].x = bb.x; c2[nt].y = bb.y;
            c2[nt].z = bb.x; c2[nt].w = bb.y;
        }
#pragma unroll
        for (int p = 0; p < 8; p++) {
            uint32_t a0 = paf[p][0], a1 = paf[p][1], a2 = paf[p][2], a3 = paf[p][3];
#pragma unroll
            for (int ntp = 0; ntp < 8; ntp++) {
                uint4 b = w2s[(p * 8 + ntp) * 32 + lane];
                mma_f16(c2[2 * ntp],     a0, a1, a2, a3, b.x, b.y);
                mma_f16(c2[2 * ntp + 1], a0, a1, a2, a3, b.z, b.w);
            }
        }
        __syncwarp();

        {
            const int cq  = (t >> 1) * 4;
            const bool odd = (t & 1);
            const int srow = g + (odd ? 8 : 0);
#pragma unroll
            for (int nt = 0; nt < 16; nt++) {
                float s0 = odd ? c2[nt].x : c2[nt].z;
                float s1 = odd ? c2[nt].y : c2[nt].w;
                float r0s = __shfl_xor_sync(0xffffffffu, s0, 1);
                float r1s = __shfl_xor_sync(0xffffffffu, s1, 1);
                float4 v;
                if (!odd) { v.x = c2[nt].x; v.y = c2[nt].y; v.z = r0s; v.w = r1s; }
                else      { v.x = r0s; v.y = r1s; v.z = c2[nt].z; v.w = c2[nt].w; }
                *(float4*)(tw + srow * 132 + nt * 8 + cq) = v;
            }
        }
        __syncwarp();

#pragma unroll 4
        for (int el = 0; el < 16; el++) {
            float4 v = *(const float4*)(tw + el * 132 + lane * 4);
            *(float4*)(out + (size_t)(r0 + el) * NB + lane * 4) = v;
        }
        __syncwarp();
    }
}

extern "C" void kernel_launch(void* const* d_in, const int* in_sizes, int n_in,
                              void* d_out, int out_size)
{
    const float* x       = (const float*)d_in[0];
    const float* f_ij    = (const float*)d_in[1];
    const float* rcut_ij = (const float*)d_in[2];
    const int*   idx_i   = (const int*)d_in[3];
    const int*   idx_j   = (const int*)d_in[4];
    const float* W_in2f  = (const float*)d_in[5];
    const float* W_filt1 = (const float*)d_in[6];
    const float* b_filt1 = (const float*)d_in[7];
    const float* W_filt2 = (const float*)d_in[8];
    const float* b_filt2 = (const float*)d_in[9];
    const float* W_out1  = (const float*)d_in[10];
    const float* b_out1  = (const float*)d_in[11];
    const float* W_out2  = (const float*)d_in[12];
    const float* b_out2  = (const float*)d_in[13];
    float* out = (float*)d_out;

    void* p_agg = nullptr;
    cudaGetSymbolAddress(&p_agg, g_agg);
    float* agg = (float*)p_agg;

    int nsm = 148;
    cudaDeviceGetAttribute(&nsm, cudaDevAttrMultiProcessorCount, 0);

    cudaFuncSetAttribute(h_kernel,
                         cudaFuncAttributeMaxDynamicSharedMemorySize, H_SMEMB);
    cudaFuncSetAttribute(edge_kernel,
                         cudaFuncAttributeMaxDynamicSharedMemorySize, E_SMEMB);
    cudaFuncSetAttribute(out_kernel,
                         cudaFuncAttributeMaxDynamicSharedMemorySize, O_SMEMB);

    // 0) pack weights + zero counters
    prep_kernel<<<40, 256>>>(W_filt1, W_filt2, W_in2f, W_out1, W_out2);
    // 1) counting sort of edges by idx_i
    hist_kernel<<<nsm, 256>>>(idx_i);
    scan_kernel<<<1, SCAN_T>>>();
    scatter_kernel<<<nsm, 256>>>(idx_i, idx_j, rcut_ij);
    // 2) h = x @ W_in2f -> fp16, zero agg
    h_kernel<<<nsm, HT, H_SMEMB>>>(x, agg);
    // 3) fused edge kernel (sorted, segmented reduce)
    edge_kernel<<<nsm, ET, E_SMEMB>>>(f_ij, b_filt1, b_filt2);
    // 4) fused output MLP
    out_kernel<<<nsm, OT, O_SMEMB>>>(agg, b_out1, b_out2, out);
}

// round 16
// speedup vs baseline: 1.4576x; 1.4576x over previous
#include <cuda_runtime.h>
#include <cuda_fp16.h>
#include <cstdint>

// Problem constants
#define N_ATOMS 20000
#define N_EDGES 640000
#define NB      128
#define N_RBF   20

// -------- device scratch --------
__device__ __half g_hh[N_ATOMS * NB];      // h in fp16
__device__ float  g_agg[N_ATOMS * NB];
// packed weight fragments (filled by prep_kernel)
__device__ uint2 gPW1[2 * 16 * 32];        // edge layer1
__device__ uint4 gPW2[8 * 8 * 32];         // edge layer2 (nt-paired)
__device__ uint4 gPWH[8 * 8 * 32];         // h kernel W_in2f
__device__ uint4 gPO1[8 * 8 * 32];         // out layer1
__device__ uint4 gPO2[8 * 8 * 32];         // out layer2

#define LN2F     0.69314718055994531f
#define LOG2EF   1.4426950408889634f
__device__ __forceinline__ float ssp_fast(float x) {
    float u = fabsf(x) * -LOG2EF;
    float e; asm("ex2.approx.f32 %0, %1;" : "=f"(e) : "f"(u));
    float l; asm("lg2.approx.f32 %0, %1;" : "=f"(l) : "f"(1.0f + e));
    return fmaf(LN2F, l - 1.0f, fmaxf(x, 0.0f));
}

__device__ __forceinline__ uint32_t h2pack(float lo, float hi) {
    __half2 h = __floats2half2_rn(lo, hi);
    return *(uint32_t*)&h;
}
__device__ __forceinline__ float2 h2unpack(uint32_t u) {
    __half2 h = *(__half2*)&u;
    return __half22float2(h);
}

// m16n8k16 f16 mma, f32 accumulate
__device__ __forceinline__ void mma_f16(float4& c,
                                        uint32_t a0, uint32_t a1, uint32_t a2, uint32_t a3,
                                        uint32_t b0, uint32_t b1) {
    asm volatile(
        "mma.sync.aligned.m16n8k16.row.col.f32.f16.f16.f32 "
        "{%0,%1,%2,%3}, {%4,%5,%6,%7}, {%8,%9}, {%0,%1,%2,%3};"
        : "+f"(c.x), "+f"(c.y), "+f"(c.z), "+f"(c.w)
        : "r"(a0), "r"(a1), "r"(a2), "r"(a3), "r"(b0), "r"(b1));
}

__device__ __forceinline__ void red_v4(float* p, float a, float b, float c, float d) {
    asm volatile("red.global.add.v4.f32 [%0], {%1, %2, %3, %4};"
                 :: "l"(p), "f"(a), "f"(b), "f"(c), "f"(d) : "memory");
}

// ======================= prep kernel: pack weight fragments once =======================
__global__ void prep_kernel(const float* __restrict__ W1e, const float* __restrict__ W2e,
                            const float* __restrict__ Wh,  const float* __restrict__ Wo1,
                            const float* __restrict__ Wo2)
{
    const int tid = blockIdx.x * blockDim.x + threadIdx.x;
    const int stride = gridDim.x * blockDim.x;

    for (int i = tid; i < 2 * 16 * 32; i += stride) {
        int p1 = i >> 9, nt = (i >> 5) & 15, l = i & 31;
        int gg = l >> 2, tt = l & 3;
        int n = nt * 8 + gg;
        int k0 = p1 * 16 + 2 * tt;
        float w00 = (k0     < N_RBF) ? W1e[k0 * NB + n]       : 0.0f;
        float w01 = (k0 + 1 < N_RBF) ? W1e[(k0 + 1) * NB + n] : 0.0f;
        float w10 = (k0 + 8 < N_RBF) ? W1e[(k0 + 8) * NB + n] : 0.0f;
        float w11 = (k0 + 9 < N_RBF) ? W1e[(k0 + 9) * NB + n] : 0.0f;
        uint2 v; v.x = h2pack(w00, w01); v.y = h2pack(w10, w11);
        gPW1[i] = v;
    }
    for (int i = tid; i < 8 * 8 * 32; i += stride) {
        int p = i >> 8, ntp = (i >> 5) & 7, l = i & 31;
        int gg = l >> 2, tt = l & 3;
        int k0 = p * 16 + 2 * tt;
        int nE = (2 * ntp) * 8 + gg, nO = nE + 8;
        uint4 v;
#define PACK4(W) do { \
        v.x = h2pack(W[k0 * NB + nE], W[(k0 + 1) * NB + nE]); \
        v.y = h2pack(W[(k0 + 8) * NB + nE], W[(k0 + 9) * NB + nE]); \
        v.z = h2pack(W[k0 * NB + nO], W[(k0 + 1) * NB + nO]); \
        v.w = h2pack(W[(k0 + 8) * NB + nO], W[(k0 + 9) * NB + nO]); } while (0)
        PACK4(W2e); gPW2[i] = v;
        PACK4(Wh);  gPWH[i] = v;
        PACK4(Wo1); gPO1[i] = v;
        PACK4(Wo2); gPO2[i] = v;
#undef PACK4
    }
}

// ======================= h kernel (fp16 mma) -> g_hh (half) + agg zeroing ================
#define HW 12
#define HT (HW * 32)
#define H_SMEMB (32768 + HW * 4224)

__global__ __launch_bounds__(HT, 1) void h_kernel(
    const float* __restrict__ x, float* __restrict__ agg)
{
    extern __shared__ char smc[];
    uint4* ws = (uint4*)smc;
    const int tid  = threadIdx.x;
    const int warp = tid >> 5;
    const int lane = tid & 31;
    const int g    = lane >> 2;
    const int t    = lane & 3;

    for (int i = tid; i < 2048; i += HT) ws[i] = gPWH[i];
    __syncthreads();

    __half* tw = (__half*)(smc + 32768 + warp * 4224);   // 16 rows x 132 halfs
    const int ngroups = N_ATOMS / 16;   // 1250

    for (int grp = blockIdx.x * HW + warp; grp < ngroups; grp += gridDim.x * HW) {
        const int r0 = grp * 16;

        uint32_t af[8][4];
#pragma unroll
        for (int p = 0; p < 8; p++) {
            const float* r0p = x + (size_t)(r0 + g) * NB + p * 16;
            const float* r1p = r0p + 8 * NB;
            float2 x0 = *(const float2*)(r0p + 2 * t);
            float2 x1 = *(const float2*)(r1p + 2 * t);
            float2 x2 = *(const float2*)(r0p + 2 * t + 8);
            float2 x3 = *(const float2*)(r1p + 2 * t + 8);
            af[p][0] = h2pack(x0.x, x0.y);
            af[p][1] = h2pack(x1.x, x1.y);
            af[p][2] = h2pack(x2.x, x2.y);
            af[p][3] = h2pack(x3.x, x3.y);
        }

        float4 c[16];
#pragma unroll
        for (int nt = 0; nt < 16; nt++) c[nt] = make_float4(0.f, 0.f, 0.f, 0.f);
#pragma unroll
        for (int p = 0; p < 8; p++) {
            uint32_t a0 = af[p][0], a1 = af[p][1], a2 = af[p][2], a3 = af[p][3];
#pragma unroll
            for (int ntp = 0; ntp < 8; ntp++) {
                uint4 b = ws[(p * 8 + ntp) * 32 + lane];
                mma_f16(c[2 * ntp],     a0, a1, a2, a3, b.x, b.y);
                mma_f16(c[2 * ntp + 1], a0, a1, a2, a3, b.z, b.w);
            }
        }
        __syncwarp();

        // pair-swap -> fp16 tile rows
        {
            const int cq  = (t >> 1) * 4;
            const bool odd = (t & 1);
            const int srow = g + (odd ? 8 : 0);
#pragma unroll
            for (int nt = 0; nt < 16; nt++) {
                float s0 = odd ? c[nt].x : c[nt].z;
                float s1 = odd ? c[nt].y : c[nt].w;
                float r0s = __shfl_xor_sync(0xffffffffu, s0, 1);
                float r1s = __shfl_xor_sync(0xffffffffu, s1, 1);
                float4 v;
                if (!odd) { v.x = c[nt].x; v.y = c[nt].y; v.z = r0s; v.w = r1s; }
                else      { v.x = r0s; v.y = r1s; v.z = c[nt].z; v.w = c[nt].w; }
                uint2 pk; pk.x = h2pack(v.x, v.y); pk.y = h2pack(v.z, v.w);
                *(uint2*)(tw + srow * 132 + nt * 8 + cq) = pk;
            }
        }
        __syncwarp();

        // coalesced half row store + agg zero
        const float4 z4 = make_float4(0.f, 0.f, 0.f, 0.f);
#pragma unroll 4
        for (int el = 0; el < 16; el++) {
            uint2 v = *(const uint2*)(tw + el * 132 + lane * 4);
            ((uint2*)(g_hh + (size_t)(r0 + el) * NB))[lane] = v;
            *(float4*)(agg + (size_t)(r0 + el) * NB + lane * 4) = z4;
        }
        __syncwarp();
    }
}

// ======================= fused edge kernel (M=32 per warp, fp16 tiles) — R14 proven =====
#define EW 12
#define ET (EW * 32)
#define E_OUTB 41472
#define E_SMEMB (E_OUTB + EW * 8448)

__global__ __launch_bounds__(ET, 1) void edge_kernel(
    const float* __restrict__ f_ij, const float* __restrict__ rcut,
    const int* __restrict__ idx_i, const int* __restrict__ idx_j,
    const float* __restrict__ b1, const float* __restrict__ b2)
{
    extern __shared__ char smc[];
    uint2* w1s = (uint2*)smc;
    uint4* w2s = (uint4*)(smc + 8192);
    float* b1s = (float*)(smc + 40960);
    const int tid  = threadIdx.x;
    const int warp = tid >> 5;
    const int lane = tid & 31;
    const int g    = lane >> 2;
    const int t    = lane & 3;

    for (int i = tid; i < 1024; i += ET) w1s[i] = gPW1[i];
    for (int i = tid; i < 2048; i += ET) w2s[i] = gPW2[i];
    for (int i = tid; i < NB; i += ET) b1s[i] = b1[i];
    __syncthreads();

    __half* outw = (__half*)(smc + E_OUTB + warp * 8448);  // 32 rows x 132 halfs
    const float4 b2v = *(const float4*)(b2 + lane * 4);
    const int cq  = (t >> 1) * 4;
    const bool odd = (t & 1);
    const int ngroups = N_EDGES / 32;  // 20000

    for (int grp = blockIdx.x * EW + warp; grp < ngroups; grp += gridDim.x * EW) {
        const int e0 = grp * 32;

        const float rc_l = __ldg(rcut + e0 + lane);
        const int   ji_l = __ldg(idx_j + e0 + lane);
        const int   ii_l = __ldg(idx_i + e0 + lane);

        uint32_t A[2][6];
#pragma unroll
        for (int s = 0; s < 2; s++) {
            const float* fr0 = f_ij + (size_t)(e0 + 16 * s + g) * N_RBF;
            const float* fr1 = fr0 + 8 * N_RBF;
            float2 q00 = *(const float2*)(fr0 + 2 * t);
            float2 q01 = *(const float2*)(fr1 + 2 * t);
            float2 q02 = *(const float2*)(fr0 + 2 * t + 8);
            float2 q03 = *(const float2*)(fr1 + 2 * t + 8);
            float2 q10 = make_float2(0.f, 0.f), q11 = make_float2(0.f, 0.f);
            if (t < 2) {
                q10 = *(const float2*)(fr0 + 2 * t + 16);
                q11 = *(const float2*)(fr1 + 2 * t + 16);
            }
            A[s][0] = h2pack(q00.x, q00.y); A[s][1] = h2pack(q01.x, q01.y);
            A[s][2] = h2pack(q02.x, q02.y); A[s][3] = h2pack(q03.x, q03.y);
            A[s][4] = h2pack(q10.x, q10.y); A[s][5] = h2pack(q11.x, q11.y);
        }

        // ---- layer 1 in quarters (4 nt each), both subsets share B loads ----
        uint32_t paf[2][8][4];
#pragma unroll
        for (int qt = 0; qt < 4; qt++) {
            float4 c1[2][4];
#pragma unroll
            for (int j = 0; j < 4; j++) {
                float2 bb = *(const float2*)(b1s + (4 * qt + j) * 8 + 2 * t);
#pragma unroll
                for (int s = 0; s < 2; s++) {
                    c1[s][j].x = bb.x; c1[s][j].y = bb.y;
                    c1[s][j].z = bb.x; c1[s][j].w = bb.y;
                }
            }
#pragma unroll
            for (int j = 0; j < 4; j++) {
                const int nt = 4 * qt + j;
                uint2 b0  = w1s[nt * 32 + lane];
                uint2 b1f = w1s[(16 + nt) * 32 + lane];
#pragma unroll
                for (int s = 0; s < 2; s++) {
                    mma_f16(c1[s][j], A[s][0], A[s][1], A[s][2], A[s][3], b0.x, b0.y);
                    mma_f16(c1[s][j], A[s][4], A[s][5], 0u, 0u, b1f.x, b1f.y);
                }
            }
#pragma unroll
            for (int s = 0; s < 2; s++)
#pragma unroll
                for (int jj = 0; jj < 2; jj++) {
                    const int p = 2 * qt + jj;
                    paf[s][p][0] = h2pack(ssp_fast(c1[s][2 * jj].x),     ssp_fast(c1[s][2 * jj].y));
                    paf[s][p][1] = h2pack(ssp_fast(c1[s][2 * jj].z),     ssp_fast(c1[s][2 * jj].w));
                    paf[s][p][2] = h2pack(ssp_fast(c1[s][2 * jj + 1].x), ssp_fast(c1[s][2 * jj + 1].y));
                    paf[s][p][3] = h2pack(ssp_fast(c1[s][2 * jj + 1].z), ssp_fast(c1[s][2 * jj + 1].w));
                }
        }
        __syncwarp();   // previous group's outw fully consumed before overwrite

        // ---- layer 2 in quarters; pair-swap each quarter to fp16 outw ----
#pragma unroll
        for (int qt = 0; qt < 4; qt++) {
            float4 c2[2][4];
#pragma unroll
            for (int s = 0; s < 2; s++)
#pragma unroll
                for (int j = 0; j < 4; j++) c2[s][j] = make_float4(0.f, 0.f, 0.f, 0.f);
#pragma unroll
            for (int p = 0; p < 8; p++) {
#pragma unroll
                for (int jj = 0; jj < 2; jj++) {
                    const int ntp = 2 * qt + jj;
                    uint4 b = w2s[(p * 8 + ntp) * 32 + lane];
#pragma unroll
                    for (int s = 0; s < 2; s++) {
                        mma_f16(c2[s][2 * jj],     paf[s][p][0], paf[s][p][1],
                                paf[s][p][2], paf[s][p][3], b.x, b.y);
                        mma_f16(c2[s][2 * jj + 1], paf[s][p][0], paf[s][p][1],
                                paf[s][p][2], paf[s][p][3], b.z, b.w);
                    }
                }
            }
#pragma unroll
            for (int s = 0; s < 2; s++) {
                const int row = 16 * s + g + (odd ? 8 : 0);
#pragma unroll
                for (int j = 0; j < 4; j++) {
                    const int nt = 4 * qt + j;
                    float s0 = odd ? c2[s][j].x : c2[s][j].z;
                    float s1 = odd ? c2[s][j].y : c2[s][j].w;
                    float r0 = __shfl_xor_sync(0xffffffffu, s0, 1);
                    float r1 = __shfl_xor_sync(0xffffffffu, s1, 1);
                    float4 v;
                    if (!odd) { v.x = c2[s][j].x; v.y = c2[s][j].y; v.z = r0; v.w = r1; }
                    else      { v.x = r0; v.y = r1; v.z = c2[s][j].z; v.w = c2[s][j].w; }
                    uint2 pk; pk.x = h2pack(v.x, v.y); pk.y = h2pack(v.z, v.w);
                    *(uint2*)(outw + row * 132 + nt * 8 + cq) = pk;
                }
            }
        }
        __syncwarp();

        // ---- row-wise epilogue: 32 edges, one full row per warp-instr ----
#pragma unroll 4
        for (int el = 0; el < 32; el++) {
            float rc = __shfl_sync(0xffffffffu, rc_l, el);
            int   ji = __shfl_sync(0xffffffffu, ji_l, el);
            int   ii = __shfl_sync(0xffffffffu, ii_l, el);
            uint2 pv = *(const uint2*)(outw + el * 132 + lane * 4);
            float2 f0 = h2unpack(pv.x), f1 = h2unpack(pv.y);
            uint2 ph = __ldg((const uint2*)(g_hh + (size_t)ji * NB) + lane);
            float2 g0 = h2unpack(ph.x), g1 = h2unpack(ph.y);
            red_v4(g_agg + (size_t)ii * NB + lane * 4,
                   (f0.x + b2v.x) * rc * g0.x,
                   (f0.y + b2v.y) * rc * g0.y,
                   (f1.x + b2v.z) * rc * g1.x,
                   (f1.y + b2v.w) * rc * g1.y);
        }
        __syncwarp();
    }
}

// ======================= fused out kernel (fp16 mma, register-halved, OW=12) ============
#define OW 12
#define OT (OW * 32)
#define O_TWB 66560
#define O_SMEMB (O_TWB + OW * 8448)

__global__ __launch_bounds__(OT, 1) void out_kernel(
    const float* __restrict__ A,     // g_agg
    const float* __restrict__ b1, const float* __restrict__ b2,
    float* __restrict__ out)
{
    extern __shared__ char smc[];
    uint4* w1s = (uint4*)smc;
    uint4* w2s = (uint4*)(smc + 32768);
    float* b1s = (float*)(smc + 65536);
    float* b2s = (float*)(smc + 66048);
    const int tid  = threadIdx.x;
    const int warp = tid >> 5;
    const int lane = tid & 31;
    const int g    = lane >> 2;
    const int t    = lane & 3;

    for (int i = tid; i < 2048; i += OT) { w1s[i] = gPO1[i]; w2s[i] = gPO2[i]; }
    for (int i = tid; i < NB; i += OT) { b1s[i] = b1[i]; b2s[i] = b2[i]; }
    __syncthreads();

    float* tw = (float*)(smc + O_TWB + warp * 8448);   // 16 rows x 132 floats
    const int cq  = (t >> 1) * 4;
    const bool odd = (t & 1);
    const int srow = g + (odd ? 8 : 0);
    const int ngroups = N_ATOMS / 16;   // 1250

    for (int grp = blockIdx.x * OW + warp; grp < ngroups; grp += gridDim.x * OW) {
        const int r0 = grp * 16;

        uint32_t af[8][4];
#pragma unroll
        for (int p = 0; p < 8; p++) {
            const float* r0p = A + (size_t)(r0 + g) * NB + p * 16;
            const float* r1p = r0p + 8 * NB;
            float2 x0 = *(const float2*)(r0p + 2 * t);
            float2 x1 = *(const float2*)(r1p + 2 * t);
            float2 x2 = *(const float2*)(r0p + 2 * t + 8);
            float2 x3 = *(const float2*)(r1p + 2 * t + 8);
            af[p][0] = h2pack(x0.x, x0.y);
            af[p][1] = h2pack(x1.x, x1.y);
            af[p][2] = h2pack(x2.x, x2.y);
            af[p][3] = h2pack(x3.x, x3.y);
        }

        // ---- layer 1 in two n-halves; build paf incrementally ----
        uint32_t paf[8][4];
#pragma unroll
        for (int hh = 0; hh < 2; hh++) {
            float4 c1[8];
#pragma unroll
            for (int j = 0; j < 8; j++) {
                float2 bb = *(const float2*)(b1s + (8 * hh + j) * 8 + 2 * t);
                c1[j].x = bb.x; c1[j].y = bb.y;
                c1[j].z = bb.x; c1[j].w = bb.y;
            }
#pragma unroll
            for (int p = 0; p < 8; p++) {
                uint32_t a0 = af[p][0], a1 = af[p][1], a2 = af[p][2], a3 = af[p][3];
#pragma unroll
                for (int jj = 0; jj < 4; jj++) {
                    const int ntp = 4 * hh + jj;
                    uint4 b = w1s[(p * 8 + ntp) * 32 + lane];
                    mma_f16(c1[2 * jj],     a0, a1, a2, a3, b.x, b.y);
                    mma_f16(c1[2 * jj + 1], a0, a1, a2, a3, b.z, b.w);
                }
            }
#pragma unroll
            for (int jj = 0; jj < 4; jj++) {
                const int p = 4 * hh + jj;
                paf[p][0] = h2pack(ssp_fast(c1[2 * jj].x),     ssp_fast(c1[2 * jj].y));
                paf[p][1] = h2pack(ssp_fast(c1[2 * jj].z),     ssp_fast(c1[2 * jj].w));
                paf[p][2] = h2pack(ssp_fast(c1[2 * jj + 1].x), ssp_fast(c1[2 * jj + 1].y));
                paf[p][3] = h2pack(ssp_fast(c1[2 * jj + 1].z), ssp_fast(c1[2 * jj + 1].w));
            }
        }
        __syncwarp();   // previous group's tw fully consumed before overwrite

        // ---- layer 2 in two n-halves; pair-swap each half into tw ----
#pragma unroll
        for (int hh = 0; hh < 2; hh++) {
            float4 c2[8];
#pragma unroll
            for (int j = 0; j < 8; j++) {
                float2 bb = *(const float2*)(b2s + (8 * hh + j) * 8 + 2 * t);
                c2[j].x = bb.x; c2[j].y = bb.y;
                c2[j].z = bb.x; c2[j].w = bb.y;
            }
#pragma unroll
            for (int p = 0; p < 8; p++) {
                uint32_t a0 = paf[p][0], a1 = paf[p][1], a2 = paf[p][2], a3 = paf[p][3];
#pragma unroll
                for (int jj = 0; jj < 4; jj++) {
                    const int ntp = 4 * hh + jj;
                    uint4 b = w2s[(p * 8 + ntp) * 32 + lane];
                    mma_f16(c2[2 * jj],     a0, a1, a2, a3, b.x, b.y);
                    mma_f16(c2[2 * jj + 1], a0, a1, a2, a3, b.z, b.w);
                }
            }
#pragma unroll
            for (int j = 0; j < 8; j++) {
                const int nt = 8 * hh + j;
                float s0 = odd ? c2[j].x : c2[j].z;
                float s1 = odd ? c2[j].y : c2[j].w;
                float r0s = __shfl_xor_sync(0xffffffffu, s0, 1);
                float r1s = __shfl_xor_sync(0xffffffffu, s1, 1);
                float4 v;
                if (!odd) { v.x = c2[j].x; v.y = c2[j].y; v.z = r0s; v.w = r1s; }
                else      { v.x = r0s; v.y = r1s; v.z = c2[j].z; v.w = c2[j].w; }
                *(float4*)(tw + srow * 132 + nt * 8 + cq) = v;
            }
        }
        __syncwarp();

        // coalesced store: one full output row per warp-instr
#pragma unroll 4
        for (int el = 0; el < 16; el++) {
            float4 v = *(const float4*)(tw + el * 132 + lane * 4);
            *(float4*)(out + (size_t)(r0 + el) * NB + lane * 4) = v;
        }
        __syncwarp();
    }
}

extern "C" void kernel_launch(void* const* d_in, const int* in_sizes, int n_in,
                              void* d_out, int out_size)
{
    const float* x       = (const float*)d_in[0];
    const float* f_ij    = (const float*)d_in[1];
    const float* rcut_ij = (const float*)d_in[2];
    const int*   idx_i   = (const int*)d_in[3];
    const int*   idx_j   = (const int*)d_in[4];
    const float* W_in2f  = (const float*)d_in[5];
    const float* W_filt1 = (const float*)d_in[6];
    const float* b_filt1 = (const float*)d_in[7];
    const float* W_filt2 = (const float*)d_in[8];
    const float* b_filt2 = (const float*)d_in[9];
    const float* W_out1  = (const float*)d_in[10];
    const float* b_out1  = (const float*)d_in[11];
    const float* W_out2  = (const float*)d_in[12];
    const float* b_out2  = (const float*)d_in[13];
    float* out = (float*)d_out;

    void* p_agg = nullptr;
    cudaGetSymbolAddress(&p_agg, g_agg);
    float* agg = (float*)p_agg;

    int nsm = 148;
    cudaDeviceGetAttribute(&nsm, cudaDevAttrMultiProcessorCount, 0);

    cudaFuncSetAttribute(h_kernel,
                         cudaFuncAttributeMaxDynamicSharedMemorySize, H_SMEMB);
    cudaFuncSetAttribute(edge_kernel,
                         cudaFuncAttributeMaxDynamicSharedMemorySize, E_SMEMB);
    cudaFuncSetAttribute(out_kernel,
                         cudaFuncAttributeMaxDynamicSharedMemorySize, O_SMEMB);

    // 0) pack weight fragments once
    prep_kernel<<<40, 256>>>(W_filt1, W_filt2, W_in2f, W_out1, W_out2);
    // 1) h = x @ W_in2f -> fp16, zero agg
    h_kernel<<<nsm, HT, H_SMEMB>>>(x, agg);
    // 2) fused edge kernel (M=32/warp, unsorted — R14 proven)
    edge_kernel<<<nsm, ET, E_SMEMB>>>(f_ij, rcut_ij, idx_i, idx_j, b_filt1, b_filt2);
    // 3) fused output MLP (register-halved, OW=12)
    out_kernel<<<nsm, OT, O_SMEMB>>>(agg, b_out1, b_out2, out);
}